// round 14
// baseline (speedup 1.0000x reference)
#include <cuda_runtime.h>
#include <cuda_bf16.h>
#include <math.h>
#include <cstdint>

// Problem constants
#define NB 8
#define CIN 256
#define HW 65536
#define NCH 512
#define CQK 32
#define NQ 1024
#define NKV 256

// Scratch (device globals; no allocation allowed)
__device__ float g_q [(size_t)NCH * CQK * NQ];       // [b][ch][pix] fp32
__device__ float g_kf[(size_t)NCH * CQK * NQ];       // [b][ch][pix] fp32 (pre-pool)
__device__ float g_vf[(size_t)NCH * CQK * NQ];       // [b][ch][pix] fp32 (pre-pool)
__device__ uint32_t g_k2hi[(size_t)NCH * NKV * 20];  // [b][kv][20] bf16-pair hi
__device__ uint32_t g_k2lo[(size_t)NCH * NKV * 20];  // [b][kv][20] bf16-pair lo
__device__ uint32_t g_v2  [(size_t)NCH * 32 * 132];  // [b][ch][132] bf16 kv-pairs
__device__ uint32_t g_wo2 [256 * 20];                // [o][20] bf16 ch-pairs

// ===========================================================================
// helpers
// ===========================================================================
__device__ __forceinline__ uint32_t s2u32(const void* p) {
    uint32_t a;
    asm("{ .reg .u64 t; cvta.to.shared.u64 t, %1; cvt.u32.u64 %0, t; }" : "=r"(a) : "l"(p));
    return a;
}
__device__ __forceinline__ uint32_t f2bf2(float lo, float hi) {
    uint32_t r;
    asm("cvt.rn.bf16x2.f32 %0, %1, %2;" : "=r"(r) : "f"(hi), "f"(lo));
    return r;
}
__device__ __forceinline__ float bf_lo(uint32_t h) { return __uint_as_float(h << 16); }
__device__ __forceinline__ float bf_hi(uint32_t h) { return __uint_as_float(h & 0xffff0000u); }

__device__ __forceinline__ void mma16816(float* c, const uint32_t* a, uint32_t b0, uint32_t b1) {
    asm volatile(
        "mma.sync.aligned.m16n8k16.row.col.f32.bf16.bf16.f32 "
        "{%0,%1,%2,%3}, {%4,%5,%6,%7}, {%8,%9}, {%0,%1,%2,%3};"
        : "+f"(c[0]), "+f"(c[1]), "+f"(c[2]), "+f"(c[3])
        : "r"(a[0]), "r"(a[1]), "r"(a[2]), "r"(a[3]), "r"(b0), "r"(b1));
}

#define CP_ASYNC16(dst, src) \
    asm volatile("cp.async.ca.shared.global [%0], [%1], 16;" :: "r"(dst), "l"(src) : "memory")
#define CP_COMMIT() asm volatile("cp.async.commit_group;" ::: "memory")
#define CP_WAIT0()  asm volatile("cp.async.wait_group 0;" ::: "memory")

// ===========================================================================
// Kernel 1: q/k/v projection via mma.sync bf16 hi/lo 3-pass.
// 512 threads = 16 warps: warpM(2, 48 rows) x warpN(8, 32 px). K=256.
// Epilogue staged through smem for fully-coalesced 128B writes.
// ===========================================================================
#define OFF_W2HI  0
#define OFF_W2LO  50688
#define OFF_BIAS  101376
#define OFF_XS    101760
#define XS_FLOATS 8576
#define QKV_SMEM  170368

__global__ __launch_bounds__(512, 1)
void qkv_mma_kernel(const float* __restrict__ x,
                    const float* __restrict__ Wq, const float* __restrict__ bq,
                    const float* __restrict__ Wk, const float* __restrict__ bk,
                    const float* __restrict__ Wv, const float* __restrict__ bv)
{
    extern __shared__ __align__(16) char smem[];
    const uint32_t sbase = s2u32(smem);
    uint32_t* W2hi = (uint32_t*)(smem + OFF_W2HI);
    uint32_t* W2lo = (uint32_t*)(smem + OFF_W2LO);
    float*    bias = (float*)(smem + OFF_BIAS);
    float*    xsm  = (float*)(smem + OFF_XS);

    const int t = threadIdx.x;
    const int wid = t >> 5, lane = t & 31;
    const int g = lane >> 2, tig = lane & 3;
    const int warpM = wid >> 3, warpN = wid & 7;
    const int m0 = warpM * 48;
    const int n0w = warpN * 32;

    const int bid = blockIdx.x;
    const int h = bid & 255;
    const int n = bid >> 8;

    const float* xrow = x + (size_t)n * (256 * 65536) + (size_t)h * 256;

    {
        const uint32_t dstb = sbase + OFF_XS;
#pragma unroll
        for (int i = 0; i < 4; ++i) {
            int item = t + i * 512;
            int ch = item >> 6, p4 = item & 63;
            CP_ASYNC16(dstb + (uint32_t)(ch * 268 + p4 * 4) * 4,
                       xrow + (size_t)ch * 65536 + p4 * 4);
        }
        CP_COMMIT();
    }

    for (int item = t; item < 96 * 128; item += 512) {
        int m = item >> 7, kk = item & 127;
        const float* wrow = (m < 32) ? (Wq + m * 256)
                          : (m < 64) ? (Wk + (m - 32) * 256)
                                     : (Wv + (m - 64) * 256);
        float f0 = wrow[2 * kk], f1 = wrow[2 * kk + 1];
        uint32_t hi = f2bf2(f0, f1);
        uint32_t lo = f2bf2(f0 - bf_lo(hi), f1 - bf_hi(hi));
        W2hi[m * 132 + kk] = hi;
        W2lo[m * 132 + kk] = lo;
    }
    if (t < 96) bias[t] = (t < 32) ? bq[t] : (t < 64 ? bk[t - 32] : bv[t - 64]);

    float acc[3][4][4];
#pragma unroll
    for (int mt = 0; mt < 3; ++mt)
#pragma unroll
        for (int nt = 0; nt < 4; ++nt)
#pragma unroll
            for (int u = 0; u < 4; ++u) acc[mt][nt][u] = 0.f;

    CP_WAIT0();
    __syncthreads();

#pragma unroll 1
    for (int cc = 0; cc < 8; ++cc) {
        if (cc < 7) {
            const uint32_t dstb = sbase + OFF_XS + (uint32_t)(((cc + 1) & 1) * XS_FLOATS * 4);
            const float* srcb = xrow + (size_t)(cc + 1) * 32 * 65536;
#pragma unroll
            for (int i = 0; i < 4; ++i) {
                int item = t + i * 512;
                int ch = item >> 6, p4 = item & 63;
                CP_ASYNC16(dstb + (uint32_t)(ch * 268 + p4 * 4) * 4,
                           srcb + (size_t)ch * 65536 + p4 * 4);
            }
            CP_COMMIT();
        }

        const float* xsf = xsm + (cc & 1) * XS_FLOATS;
        const int kkc = cc * 16;

#pragma unroll
        for (int s = 0; s < 2; ++s) {
            const int ks = s * 16;
            const int kk0 = kkc + s * 8 + tig;

            uint32_t Ahi[3][4], Alo[3][4];
#pragma unroll
            for (int mt = 0; mt < 3; ++mt) {
                const int r0 = (m0 + mt * 16 + g) * 132;
                const int r8 = r0 + 8 * 132;
                Ahi[mt][0] = W2hi[r0 + kk0];
                Ahi[mt][1] = W2hi[r8 + kk0];
                Ahi[mt][2] = W2hi[r0 + kk0 + 4];
                Ahi[mt][3] = W2hi[r8 + kk0 + 4];
                Alo[mt][0] = W2lo[r0 + kk0];
                Alo[mt][1] = W2lo[r8 + kk0];
                Alo[mt][2] = W2lo[r0 + kk0 + 4];
                Alo[mt][3] = W2lo[r8 + kk0 + 4];
            }

#pragma unroll
            for (int nt = 0; nt < 4; ++nt) {
                const int base = (ks + 2 * tig) * 268 + n0w + nt * 8 + g;
                float x0 = xsf[base];
                float x1 = xsf[base + 268];
                float x2 = xsf[base + 8 * 268];
                float x3 = xsf[base + 9 * 268];
                uint32_t bhi0 = f2bf2(x0, x1);
                uint32_t bhi1 = f2bf2(x2, x3);
                uint32_t blo0 = f2bf2(x0 - bf_lo(bhi0), x1 - bf_hi(bhi0));
                uint32_t blo1 = f2bf2(x2 - bf_lo(bhi1), x3 - bf_hi(bhi1));
#pragma unroll
                for (int mt = 0; mt < 3; ++mt) {
                    mma16816(acc[mt][nt], Ahi[mt], bhi0, bhi1);
                    mma16816(acc[mt][nt], Ahi[mt], blo0, blo1);
                    mma16816(acc[mt][nt], Alo[mt], bhi0, bhi1);
                }
            }
        }

        if (cc < 7) CP_WAIT0();
        __syncthreads();
    }

    // ---- epilogue: stage to smem (aliases dead W2), coalesced 128B writes ----
    {
        float* SS = (float*)smem;   // [96][260]
#pragma unroll
        for (int mt = 0; mt < 3; ++mt) {
            const int mbase = m0 + mt * 16;
#pragma unroll
            for (int nt = 0; nt < 4; ++nt) {
                const int w = n0w + nt * 8 + tig * 2;
                SS[(mbase + g) * 260 + w]         = acc[mt][nt][0];
                SS[(mbase + g) * 260 + w + 1]     = acc[mt][nt][1];
                SS[(mbase + 8 + g) * 260 + w]     = acc[mt][nt][2];
                SS[(mbase + 8 + g) * 260 + w + 1] = acc[mt][nt][3];
            }
        }
        __syncthreads();

        const int gy = h >> 5, ii = h & 31;
#pragma unroll 4
        for (int it = 0; it < 48; ++it) {
            const int pair = wid * 48 + it;
            const int o = pair >> 3, gx = pair & 7;
            const float v = SS[o * 260 + gx * 32 + lane] + bias[o];
            float* arr = (o < 32) ? g_q : (o < 64) ? g_kf : g_vf;
            const int ch = o & 31;
            const int b = n * 64 + gy * 8 + gx;
            arr[((size_t)(b * 32 + ch)) * 1024 + ii * 32 + lane] = v;
        }
    }
}

// ===========================================================================
// Kernel 2: pool + pack (unchanged, passing)
// ===========================================================================
#define POOL_STRIDE 1028
#define POOL_SMEM  (32 * POOL_STRIDE * 4)

__global__ __launch_bounds__(256)
void pool_pack_kernel(const float* __restrict__ Wo)
{
    extern __shared__ float ps[];
    const int t = threadIdx.x;
    const int b = blockIdx.x;

    if (b < 512) {
        const float4* src = (const float4*)(g_kf + (size_t)b * 32768);
        for (int i = t; i < 8192; i += 256) {
            int ch = i >> 8, p4 = i & 255;
            ((float4*)ps)[ch * 257 + p4] = src[i];
        }
        __syncthreads();
        for (int i = t; i < 4096; i += 256) {
            int kp = i & 15, kv = i >> 4;
            int pi = kv >> 4, pj = kv & 15;
            const float* r0 = ps + (2 * kp) * POOL_STRIDE + pi * 64 + 2 * pj;
            const float* r1 = r0 + POOL_STRIDE;
            float m0 = fmaxf(fmaxf(r0[0], r0[1]), fmaxf(r0[32], r0[33]));
            float m1 = fmaxf(fmaxf(r1[0], r1[1]), fmaxf(r1[32], r1[33]));
            uint32_t hi = f2bf2(m0, m1);
            uint32_t lo = f2bf2(m0 - bf_lo(hi), m1 - bf_hi(hi));
            g_k2hi[(size_t)b * 5120 + kv * 20 + kp] = hi;
            g_k2lo[(size_t)b * 5120 + kv * 20 + kp] = lo;
        }
        __syncthreads();
        const float4* srcv = (const float4*)(g_vf + (size_t)b * 32768);
        for (int i = t; i < 8192; i += 256) {
            int ch = i >> 8, p4 = i & 255;
            ((float4*)ps)[ch * 257 + p4] = srcv[i];
        }
        __syncthreads();
        for (int i = t; i < 4096; i += 256) {
            int kvp = i & 127, ch = i >> 7;
            const float* rr = ps + ch * POOL_STRIDE;
            int kv0 = 2 * kvp, kv1 = kv0 + 1;
            int b0 = (kv0 >> 4) * 64 + 2 * (kv0 & 15);
            int b1i = (kv1 >> 4) * 64 + 2 * (kv1 & 15);
            float v0 = fmaxf(fmaxf(rr[b0], rr[b0 + 1]), fmaxf(rr[b0 + 32], rr[b0 + 33]));
            float v1 = fmaxf(fmaxf(rr[b1i], rr[b1i + 1]), fmaxf(rr[b1i + 32], rr[b1i + 33]));
            g_v2[(size_t)b * 4224 + ch * 132 + kvp] = f2bf2(v0, v1);
        }
    } else {
        for (int i = t; i < 4096; i += 256) {
            int kp = i & 15, o = i >> 4;
            g_wo2[o * 20 + kp] = f2bf2(Wo[o * 32 + 2 * kp], Wo[o * 32 + 2 * kp + 1]);
        }
    }
}

// ===========================================================================
// Kernel 3: attention on mma.sync, 512 threads = 16 warps.
// Stage-C output staged through smem (P2 alias) for coalesced out/x traffic.
// ===========================================================================
#define AOF_Q2HI 0          // [128][20] u32 (aliased by ao2hi)
#define AOF_Q2LO 10240
#define AOF_K2HI 20480      // [256][20] u32 (aliased by AOP after stage A)
#define AOF_K2LO 40960
#define AOF_P2   61440      // [128][132] u32 (aliased by SC in stage C)
#define AOF_V2   129024     // [32][132] u32
#define AOF_WO2  145920     // [256][20] u32
#define AOF_RS   166400     // [128][9] float
#define ATTN_SMEM 171008

__global__ __launch_bounds__(512, 1)
void attn_mma_kernel(const float* __restrict__ bo,
                     const float* __restrict__ gamma,
                     const float* __restrict__ x, float* __restrict__ out)
{
    extern __shared__ __align__(16) char smem[];
    const uint32_t sbase = s2u32(smem);
    uint32_t* Q2hi = (uint32_t*)(smem + AOF_Q2HI);
    uint32_t* Q2lo = (uint32_t*)(smem + AOF_Q2LO);
    uint32_t* K2hi = (uint32_t*)(smem + AOF_K2HI);
    uint32_t* K2lo = (uint32_t*)(smem + AOF_K2LO);
    uint32_t* P2   = (uint32_t*)(smem + AOF_P2);
    uint32_t* V2   = (uint32_t*)(smem + AOF_V2);
    uint32_t* Wo2  = (uint32_t*)(smem + AOF_WO2);
    float*    RS   = (float*)(smem + AOF_RS);
    float*    AOP  = (float*)(smem + AOF_K2HI);   // [2][128][34] alias (K dead)
    float*    SC   = (float*)(smem + AOF_P2);     // [128][132] alias (P dead)

    const int t = threadIdx.x;
    const int wid = t >> 5, lane = t & 31;
    const int g = lane >> 2, tig = lane & 3;

    const int bid = blockIdx.x;
    const int b = bid >> 3;
    const int pixbase = (bid & 7) << 7;

    // ---- Phase 0: cp.async K2/V2/Wo2, convert Q ----
    for (int c = t; c < 1024; c += 512) {
        int row = c >> 2, part = c & 3;
        CP_ASYNC16(sbase + AOF_K2HI + row * 80 + part * 16,
                   g_k2hi + (size_t)b * 5120 + row * 20 + part * 4);
        CP_ASYNC16(sbase + AOF_K2LO + row * 80 + part * 16,
                   g_k2lo + (size_t)b * 5120 + row * 20 + part * 4);
        CP_ASYNC16(sbase + AOF_WO2 + row * 80 + part * 16,
                   g_wo2 + row * 20 + part * 4);
    }
    for (int c = t; c < 1056; c += 512)
        CP_ASYNC16(sbase + AOF_V2 + c * 16, g_v2 + (size_t)b * 4224 + c * 4);
    CP_COMMIT();

    {
        const float* gq = g_q + (size_t)b * 32768;
        for (int item = t; item < 2048; item += 512) {
            int kp = item >> 7, pix = item & 127;
            float f0 = gq[(2 * kp) * 1024 + pixbase + pix];
            float f1 = gq[(2 * kp + 1) * 1024 + pixbase + pix];
            uint32_t hi = f2bf2(f0, f1);
            Q2hi[pix * 20 + kp] = hi;
            Q2lo[pix * 20 + kp] = f2bf2(f0 - bf_lo(hi), f1 - bf_hi(hi));
        }
    }
    CP_WAIT0();
    __syncthreads();

    // ---- Stage A: E = Q^T K (3-pass), no-max exp, P -> smem, row sums ----
    {
        const int warpM = wid >> 3, warpN = wid & 7;
        const int m0 = warpM * 64;
        float acc[4][4][4];
#pragma unroll
        for (int mt = 0; mt < 4; ++mt)
#pragma unroll
            for (int nt = 0; nt < 4; ++nt)
#pragma unroll
                for (int u = 0; u < 4; ++u) acc[mt][nt][u] = 0.f;

#pragma unroll
        for (int ks = 0; ks < 2; ++ks) {
            const int kk = ks * 8 + tig;
            uint32_t Ahi[4][4], Alo[4][4];
#pragma unroll
            for (int mt = 0; mt < 4; ++mt) {
                const int r0 = (m0 + mt * 16 + g) * 20;
                const int r8 = r0 + 8 * 20;
                Ahi[mt][0] = Q2hi[r0 + kk];  Ahi[mt][1] = Q2hi[r8 + kk];
                Ahi[mt][2] = Q2hi[r0 + kk + 4]; Ahi[mt][3] = Q2hi[r8 + kk + 4];
                Alo[mt][0] = Q2lo[r0 + kk];  Alo[mt][1] = Q2lo[r8 + kk];
                Alo[mt][2] = Q2lo[r0 + kk + 4]; Alo[mt][3] = Q2lo[r8 + kk + 4];
            }
#pragma unroll
            for (int nt = 0; nt < 4; ++nt) {
                const int col = (warpN * 32 + nt * 8 + g) * 20;
                uint32_t bh0 = K2hi[col + kk], bh1 = K2hi[col + kk + 4];
                uint32_t bl0 = K2lo[col + kk], bl1 = K2lo[col + kk + 4];
#pragma unroll
                for (int mt = 0; mt < 4; ++mt) {
                    mma16816(acc[mt][nt], Ahi[mt], bh0, bh1);
                    mma16816(acc[mt][nt], Ahi[mt], bl0, bl1);
                    mma16816(acc[mt][nt], Alo[mt], bh0, bh1);
                }
            }
        }

#pragma unroll
        for (int mt = 0; mt < 4; ++mt) {
            const int rowA = (m0 + mt * 16 + g) * 132;
            const int rowB = rowA + 8 * 132;
            float sA = 0.f, sB = 0.f;
#pragma unroll
            for (int nt = 0; nt < 4; ++nt) {
                float p0 = __expf(acc[mt][nt][0]);
                float p1 = __expf(acc[mt][nt][1]);
                float p2 = __expf(acc[mt][nt][2]);
                float p3 = __expf(acc[mt][nt][3]);
                sA += p0 + p1;
                sB += p2 + p3;
                const int colu = warpN * 16 + nt * 4 + tig;
                P2[rowA + colu] = f2bf2(p0, p1);
                P2[rowB + colu] = f2bf2(p2, p3);
            }
            sA += __shfl_xor_sync(0xffffffffu, sA, 1);
            sA += __shfl_xor_sync(0xffffffffu, sA, 2);
            sB += __shfl_xor_sync(0xffffffffu, sB, 1);
            sB += __shfl_xor_sync(0xffffffffu, sB, 2);
            if (tig == 0) {
                RS[(m0 + mt * 16 + g) * 9 + warpN] = sA;
                RS[(m0 + mt * 16 + 8 + g) * 9 + warpN] = sB;
            }
        }
    }
    __syncthreads();

    // ---- Stage B: warp = 16 px x 32 ch over its 128-kv half ----
    {
        const int pxg = wid >> 1, kvh = wid & 1;
        const int m0b = pxg * 16;
        float accB[4][4];
#pragma unroll
        for (int n2 = 0; n2 < 4; ++n2)
#pragma unroll
            for (int u = 0; u < 4; ++u) accB[n2][u] = 0.f;

#pragma unroll
        for (int j = 0; j < 8; ++j) {
            const int kt = kvh * 8 + j;
            uint32_t a[4];
            a[0] = P2[(m0b + g) * 132 + kt * 8 + tig];
            a[1] = P2[(m0b + 8 + g) * 132 + kt * 8 + tig];
            a[2] = P2[(m0b + g) * 132 + kt * 8 + 4 + tig];
            a[3] = P2[(m0b + 8 + g) * 132 + kt * 8 + 4 + tig];
#pragma unroll
            for (int n2 = 0; n2 < 4; ++n2) {
                uint32_t b0 = V2[(n2 * 8 + g) * 132 + kt * 8 + tig];
                uint32_t b1 = V2[(n2 * 8 + g) * 132 + kt * 8 + 4 + tig];
                mma16816(accB[n2], a, b0, b1);
            }
        }

        float* aw = AOP + kvh * (128 * 34);
#pragma unroll
        for (int n2 = 0; n2 < 4; ++n2) {
            const int ch = n2 * 8 + 2 * tig;
            aw[(m0b + g) * 34 + ch]     = accB[n2][0];
            aw[(m0b + g) * 34 + ch + 1] = accB[n2][1];
            aw[(m0b + 8 + g) * 34 + ch]     = accB[n2][2];
            aw[(m0b + 8 + g) * 34 + ch + 1] = accB[n2][3];
        }
    }
    __syncthreads();

    // ---- reduce halves, normalize, pack ao hi/lo into Q2 alias ----
    for (int item = t; item < 2048; item += 512) {
        const int pix = item & 127, kp = item >> 7;
        float inv = 0.f;
#pragma unroll
        for (int w = 0; w < 8; ++w) inv += RS[pix * 9 + w];
        inv = 1.f / inv;
        float s0 = AOP[pix * 34 + 2 * kp]     + AOP[128 * 34 + pix * 34 + 2 * kp];
        float s1 = AOP[pix * 34 + 2 * kp + 1] + AOP[128 * 34 + pix * 34 + 2 * kp + 1];
        s0 *= inv; s1 *= inv;
        uint32_t hi = f2bf2(s0, s1);
        Q2hi[pix * 20 + kp] = hi;
        Q2lo[pix * 20 + kp] = f2bf2(s0 - bf_lo(hi), s1 - bf_hi(hi));
    }
    __syncthreads();   // ao ready; P2 dead from here (SC alias safe)

    // ---- Stage C: warp = 16 px x 128 o; staged coalesced epilogue ----
    {
        const int wM = wid >> 1, wN = wid & 1;
        const int m0c = wM * 16;
        float acc2[16][4];
#pragma unroll
        for (int nt = 0; nt < 16; ++nt)
#pragma unroll
            for (int u = 0; u < 4; ++u) acc2[nt][u] = 0.f;

#pragma unroll
        for (int ks = 0; ks < 2; ++ks) {
            const int kk = ks * 8 + tig;
            uint32_t Ahi[4], Alo[4];
            const int r0 = (m0c + g) * 20;
            const int r8 = r0 + 8 * 20;
            Ahi[0] = Q2hi[r0 + kk];  Ahi[1] = Q2hi[r8 + kk];
            Ahi[2] = Q2hi[r0 + kk + 4]; Ahi[3] = Q2hi[r8 + kk + 4];
            Alo[0] = Q2lo[r0 + kk];  Alo[1] = Q2lo[r8 + kk];
            Alo[2] = Q2lo[r0 + kk + 4]; Alo[3] = Q2lo[r8 + kk + 4];
#pragma unroll
            for (int nt = 0; nt < 16; ++nt) {
                const int col = (wN * 128 + nt * 8 + g) * 20;
                uint32_t b0 = Wo2[col + kk], b1 = Wo2[col + kk + 4];
                mma16816(acc2[nt], Ahi, b0, b1);
                mma16816(acc2[nt], Alo, b0, b1);
            }
        }

        const float gam = __ldg(gamma);
        const int n = b >> 6, gy = (b >> 3) & 7, gx = b & 7;
        const size_t nbase = (size_t)n * (256 * 65536);
        const int irow0 = gy * 32 + (pixbase >> 5);

#pragma unroll 1
        for (int half = 0; half < 2; ++half) {
            if (wN == half) {
#pragma unroll
                for (int nt = 0; nt < 16; ++nt) {
                    const int ol = nt * 8 + 2 * tig;
                    SC[ol * 132 + m0c + g]           = acc2[nt][0];
                    SC[(ol + 1) * 132 + m0c + g]     = acc2[nt][1];
                    SC[ol * 132 + m0c + 8 + g]       = acc2[nt][2];
                    SC[(ol + 1) * 132 + m0c + 8 + g] = acc2[nt][3];
                }
            }
            __syncthreads();

#pragma unroll 4
            for (int it = 0; it < 32; ++it) {
                const int seg = wid * 32 + it;      // 0..511
                const int ol = seg >> 2, r = seg & 3;
                const int o = half * 128 + ol;
                const int px = r * 32 + lane;
                const size_t addr = nbase + (size_t)o * 65536
                                  + (size_t)(irow0 + r) * 256 + gx * 32 + lane;
                const float v = SC[ol * 132 + px] + __ldg(bo + o);
                out[addr] = fmaf(gam, v, x[addr]);
            }
            __syncthreads();
        }
    }
}

// ---------------------------------------------------------------------------
extern "C" void kernel_launch(void* const* d_in, const int* in_sizes, int n_in,
                              void* d_out, int out_size)
{
    const float* x  = (const float*)d_in[0];
    const float* Wq = (const float*)d_in[1];
    const float* bq = (const float*)d_in[2];
    const float* Wk = (const float*)d_in[3];
    const float* bk = (const float*)d_in[4];
    const float* Wv = (const float*)d_in[5];
    const float* bv = (const float*)d_in[6];
    const float* Wo = (const float*)d_in[7];
    const float* bo = (const float*)d_in[8];
    const float* gamma = (const float*)d_in[9];
    float* out = (float*)d_out;

    cudaFuncSetAttribute(qkv_mma_kernel, cudaFuncAttributeMaxDynamicSharedMemorySize, QKV_SMEM);
    cudaFuncSetAttribute(pool_pack_kernel, cudaFuncAttributeMaxDynamicSharedMemorySize, POOL_SMEM);
    cudaFuncSetAttribute(attn_mma_kernel, cudaFuncAttributeMaxDynamicSharedMemorySize, ATTN_SMEM);

    qkv_mma_kernel<<<2048, 512, QKV_SMEM>>>(x, Wq, bq, Wk, bk, Wv, bv);
    pool_pack_kernel<<<513, 256, POOL_SMEM>>>(Wo);
    attn_mma_kernel<<<4096, 512, ATTN_SMEM>>>(bo, gamma, x, out);
}

// round 16
// speedup vs baseline: 1.4575x; 1.4575x over previous
#include <cuda_runtime.h>
#include <cuda_bf16.h>
#include <math.h>
#include <cstdint>

// Problem constants
#define NB 8
#define CIN 256
#define HW 65536
#define NCH 512
#define CQK 32
#define NQ 1024
#define NKV 256

// Scratch (device globals; no allocation allowed)
__device__ float g_q [(size_t)NCH * CQK * NQ];       // [b][ch][pix] fp32
__device__ float g_kf[(size_t)NCH * CQK * NQ];       // [b][ch][pix] fp32 (pre-pool)
__device__ float g_vf[(size_t)NCH * CQK * NQ];       // [b][ch][pix] fp32 (pre-pool)
__device__ uint32_t g_k2hi[(size_t)NCH * NKV * 20];  // [b][kv][20] bf16-pair hi
__device__ uint32_t g_k2lo[(size_t)NCH * NKV * 20];  // [b][kv][20] bf16-pair lo
__device__ uint32_t g_v2  [(size_t)NCH * 32 * 132];  // [b][ch][132] bf16 kv-pairs
__device__ uint32_t g_wo2 [256 * 20];                // [o][20] bf16 ch-pairs

// ===========================================================================
// helpers
// ===========================================================================
__device__ __forceinline__ uint32_t s2u32(const void* p) {
    uint32_t a;
    asm("{ .reg .u64 t; cvta.to.shared.u64 t, %1; cvt.u32.u64 %0, t; }" : "=r"(a) : "l"(p));
    return a;
}
__device__ __forceinline__ uint32_t f2bf2(float lo, float hi) {
    uint32_t r;
    asm("cvt.rn.bf16x2.f32 %0, %1, %2;" : "=r"(r) : "f"(hi), "f"(lo));
    return r;
}
__device__ __forceinline__ float bf_lo(uint32_t h) { return __uint_as_float(h << 16); }
__device__ __forceinline__ float bf_hi(uint32_t h) { return __uint_as_float(h & 0xffff0000u); }

__device__ __forceinline__ void mma16816(float* c, const uint32_t* a, uint32_t b0, uint32_t b1) {
    asm volatile(
        "mma.sync.aligned.m16n8k16.row.col.f32.bf16.bf16.f32 "
        "{%0,%1,%2,%3}, {%4,%5,%6,%7}, {%8,%9}, {%0,%1,%2,%3};"
        : "+f"(c[0]), "+f"(c[1]), "+f"(c[2]), "+f"(c[3])
        : "r"(a[0]), "r"(a[1]), "r"(a[2]), "r"(a[3]), "r"(b0), "r"(b1));
}

#define CP_ASYNC16(dst, src) \
    asm volatile("cp.async.ca.shared.global [%0], [%1], 16;" :: "r"(dst), "l"(src) : "memory")
#define CP_COMMIT() asm volatile("cp.async.commit_group;" ::: "memory")
#define CP_WAIT0()  asm volatile("cp.async.wait_group 0;" ::: "memory")

// ===========================================================================
// Kernel 1: q/k/v projection via mma.sync bf16 hi/lo 3-pass (round-12, 331us).
// 512 threads = 16 warps: warpM(2, 48 rows) x warpN(8, 32 px). K=256.
// ===========================================================================
#define OFF_W2HI  0
#define OFF_W2LO  50688
#define OFF_BIAS  101376
#define OFF_XS    101760
#define XS_FLOATS 8576
#define QKV_SMEM  170368

__global__ __launch_bounds__(512, 1)
void qkv_mma_kernel(const float* __restrict__ x,
                    const float* __restrict__ Wq, const float* __restrict__ bq,
                    const float* __restrict__ Wk, const float* __restrict__ bk,
                    const float* __restrict__ Wv, const float* __restrict__ bv)
{
    extern __shared__ __align__(16) char smem[];
    const uint32_t sbase = s2u32(smem);
    uint32_t* W2hi = (uint32_t*)(smem + OFF_W2HI);
    uint32_t* W2lo = (uint32_t*)(smem + OFF_W2LO);
    float*    bias = (float*)(smem + OFF_BIAS);
    float*    xsm  = (float*)(smem + OFF_XS);

    const int t = threadIdx.x;
    const int wid = t >> 5, lane = t & 31;
    const int g = lane >> 2, tig = lane & 3;
    const int warpM = wid >> 3, warpN = wid & 7;
    const int m0 = warpM * 48;
    const int n0w = warpN * 32;

    const int bid = blockIdx.x;
    const int h = bid & 255;
    const int n = bid >> 8;

    const float* xrow = x + (size_t)n * (256 * 65536) + (size_t)h * 256;

    {
        const uint32_t dstb = sbase + OFF_XS;
#pragma unroll
        for (int i = 0; i < 4; ++i) {
            int item = t + i * 512;
            int ch = item >> 6, p4 = item & 63;
            CP_ASYNC16(dstb + (uint32_t)(ch * 268 + p4 * 4) * 4,
                       xrow + (size_t)ch * 65536 + p4 * 4);
        }
        CP_COMMIT();
    }

    for (int item = t; item < 96 * 128; item += 512) {
        int m = item >> 7, kk = item & 127;
        const float* wrow = (m < 32) ? (Wq + m * 256)
                          : (m < 64) ? (Wk + (m - 32) * 256)
                                     : (Wv + (m - 64) * 256);
        float f0 = wrow[2 * kk], f1 = wrow[2 * kk + 1];
        uint32_t hi = f2bf2(f0, f1);
        uint32_t lo = f2bf2(f0 - bf_lo(hi), f1 - bf_hi(hi));
        W2hi[m * 132 + kk] = hi;
        W2lo[m * 132 + kk] = lo;
    }
    if (t < 96) bias[t] = (t < 32) ? bq[t] : (t < 64 ? bk[t - 32] : bv[t - 64]);

    float acc[3][4][4];
#pragma unroll
    for (int mt = 0; mt < 3; ++mt)
#pragma unroll
        for (int nt = 0; nt < 4; ++nt)
#pragma unroll
            for (int u = 0; u < 4; ++u) acc[mt][nt][u] = 0.f;

    CP_WAIT0();
    __syncthreads();

#pragma unroll 1
    for (int cc = 0; cc < 8; ++cc) {
        if (cc < 7) {
            const uint32_t dstb = sbase + OFF_XS + (uint32_t)(((cc + 1) & 1) * XS_FLOATS * 4);
            const float* srcb = xrow + (size_t)(cc + 1) * 32 * 65536;
#pragma unroll
            for (int i = 0; i < 4; ++i) {
                int item = t + i * 512;
                int ch = item >> 6, p4 = item & 63;
                CP_ASYNC16(dstb + (uint32_t)(ch * 268 + p4 * 4) * 4,
                           srcb + (size_t)ch * 65536 + p4 * 4);
            }
            CP_COMMIT();
        }

        const float* xsf = xsm + (cc & 1) * XS_FLOATS;
        const int kkc = cc * 16;

#pragma unroll
        for (int s = 0; s < 2; ++s) {
            const int ks = s * 16;
            const int kk0 = kkc + s * 8 + tig;

            uint32_t Ahi[3][4], Alo[3][4];
#pragma unroll
            for (int mt = 0; mt < 3; ++mt) {
                const int r0 = (m0 + mt * 16 + g) * 132;
                const int r8 = r0 + 8 * 132;
                Ahi[mt][0] = W2hi[r0 + kk0];
                Ahi[mt][1] = W2hi[r8 + kk0];
                Ahi[mt][2] = W2hi[r0 + kk0 + 4];
                Ahi[mt][3] = W2hi[r8 + kk0 + 4];
                Alo[mt][0] = W2lo[r0 + kk0];
                Alo[mt][1] = W2lo[r8 + kk0];
                Alo[mt][2] = W2lo[r0 + kk0 + 4];
                Alo[mt][3] = W2lo[r8 + kk0 + 4];
            }

#pragma unroll
            for (int nt = 0; nt < 4; ++nt) {
                const int base = (ks + 2 * tig) * 268 + n0w + nt * 8 + g;
                float x0 = xsf[base];
                float x1 = xsf[base + 268];
                float x2 = xsf[base + 8 * 268];
                float x3 = xsf[base + 9 * 268];
                uint32_t bhi0 = f2bf2(x0, x1);
                uint32_t bhi1 = f2bf2(x2, x3);
                uint32_t blo0 = f2bf2(x0 - bf_lo(bhi0), x1 - bf_hi(bhi0));
                uint32_t blo1 = f2bf2(x2 - bf_lo(bhi1), x3 - bf_hi(bhi1));
#pragma unroll
                for (int mt = 0; mt < 3; ++mt) {
                    mma16816(acc[mt][nt], Ahi[mt], bhi0, bhi1);
                    mma16816(acc[mt][nt], Ahi[mt], blo0, blo1);
                    mma16816(acc[mt][nt], Alo[mt], bhi0, bhi1);
                }
            }
        }

        if (cc < 7) CP_WAIT0();
        __syncthreads();
    }

    {
        const int gy = h >> 5, ii = h & 31;
#pragma unroll
        for (int mt = 0; mt < 3; ++mt) {
            const int mbase = m0 + mt * 16;
            const int aidx = mbase >> 5;
            float* arr = (aidx == 0) ? g_q : (aidx == 1) ? g_kf : g_vf;
            const int ch = (mbase & 31) + g;
            const float b1 = bias[mbase + g];
            const float b2 = bias[mbase + 8 + g];
#pragma unroll
            for (int nt = 0; nt < 4; ++nt) {
                const int w = n0w + nt * 8 + tig * 2;
                const int gx = w >> 5;
                const int b = n * 64 + gy * 8 + gx;
                const int pix = ii * 32 + (w & 31);
                float2* d0 = (float2*)(arr + ((size_t)(b * 32 + ch)) * 1024 + pix);
                float2* d1 = (float2*)(arr + ((size_t)(b * 32 + ch + 8)) * 1024 + pix);
                *d0 = make_float2(acc[mt][nt][0] + b1, acc[mt][nt][1] + b1);
                *d1 = make_float2(acc[mt][nt][2] + b2, acc[mt][nt][3] + b2);
            }
        }
    }
}

// ===========================================================================
// Kernel 2: pool + pack (unchanged, passing)
// ===========================================================================
#define POOL_STRIDE 1028
#define POOL_SMEM  (32 * POOL_STRIDE * 4)

__global__ __launch_bounds__(256)
void pool_pack_kernel(const float* __restrict__ Wo)
{
    extern __shared__ float ps[];
    const int t = threadIdx.x;
    const int b = blockIdx.x;

    if (b < 512) {
        const float4* src = (const float4*)(g_kf + (size_t)b * 32768);
        for (int i = t; i < 8192; i += 256) {
            int ch = i >> 8, p4 = i & 255;
            ((float4*)ps)[ch * 257 + p4] = src[i];
        }
        __syncthreads();
        for (int i = t; i < 4096; i += 256) {
            int kp = i & 15, kv = i >> 4;
            int pi = kv >> 4, pj = kv & 15;
            const float* r0 = ps + (2 * kp) * POOL_STRIDE + pi * 64 + 2 * pj;
            const float* r1 = r0 + POOL_STRIDE;
            float m0 = fmaxf(fmaxf(r0[0], r0[1]), fmaxf(r0[32], r0[33]));
            float m1 = fmaxf(fmaxf(r1[0], r1[1]), fmaxf(r1[32], r1[33]));
            uint32_t hi = f2bf2(m0, m1);
            uint32_t lo = f2bf2(m0 - bf_lo(hi), m1 - bf_hi(hi));
            g_k2hi[(size_t)b * 5120 + kv * 20 + kp] = hi;
            g_k2lo[(size_t)b * 5120 + kv * 20 + kp] = lo;
        }
        __syncthreads();
        const float4* srcv = (const float4*)(g_vf + (size_t)b * 32768);
        for (int i = t; i < 8192; i += 256) {
            int ch = i >> 8, p4 = i & 255;
            ((float4*)ps)[ch * 257 + p4] = srcv[i];
        }
        __syncthreads();
        for (int i = t; i < 4096; i += 256) {
            int kvp = i & 127, ch = i >> 7;
            const float* rr = ps + ch * POOL_STRIDE;
            int kv0 = 2 * kvp, kv1 = kv0 + 1;
            int b0 = (kv0 >> 4) * 64 + 2 * (kv0 & 15);
            int b1i = (kv1 >> 4) * 64 + 2 * (kv1 & 15);
            float v0 = fmaxf(fmaxf(rr[b0], rr[b0 + 1]), fmaxf(rr[b0 + 32], rr[b0 + 33]));
            float v1 = fmaxf(fmaxf(rr[b1i], rr[b1i + 1]), fmaxf(rr[b1i + 32], rr[b1i + 33]));
            g_v2[(size_t)b * 4224 + ch * 132 + kvp] = f2bf2(v0, v1);
        }
    } else {
        for (int i = t; i < 4096; i += 256) {
            int kp = i & 15, o = i >> 4;
            g_wo2[o * 20 + kp] = f2bf2(Wo[o * 32 + 2 * kp], Wo[o * 32 + 2 * kp + 1]);
        }
    }
}

// ===========================================================================
// Kernel 3: attention, flash-style, 256 threads = 8 warps, 2 CTAs/SM.
// Warp owns 16 px x all 256 kv: E chunk (64 kv) -> exp -> P regs -> P*V
// accumulated in regs. No P smem, no cross-warp reduce, no mid-kernel syncs.
// ===========================================================================
#define AOF_Q2HI 0          // [128][20] u32
#define AOF_Q2LO 10240
#define AOF_K2HI 20480      // [256][20] u32
#define AOF_K2LO 40960
#define AOF_V2   61440      // [32][132] u32
#define AOF_WO2  78336      // [256][20] u32
#define ATTN_SMEM 98816

__global__ __launch_bounds__(256, 2)
void attn_mma_kernel(const float* __restrict__ bo,
                     const float* __restrict__ gamma,
                     const float* __restrict__ x, float* __restrict__ out)
{
    extern __shared__ __align__(16) char smem[];
    const uint32_t sbase = s2u32(smem);
    uint32_t* Q2hi = (uint32_t*)(smem + AOF_Q2HI);
    uint32_t* Q2lo = (uint32_t*)(smem + AOF_Q2LO);
    uint32_t* K2hi = (uint32_t*)(smem + AOF_K2HI);
    uint32_t* K2lo = (uint32_t*)(smem + AOF_K2LO);
    uint32_t* V2   = (uint32_t*)(smem + AOF_V2);
    uint32_t* Wo2  = (uint32_t*)(smem + AOF_WO2);

    const int t = threadIdx.x;
    const int wid = t >> 5, lane = t & 31;
    const int g = lane >> 2, tig = lane & 3;

    const int bid = blockIdx.x;
    const int b = bid >> 3;
    const int pixbase = (bid & 7) << 7;

    // ---- Phase 0: cp.async K2/V2/Wo2, convert Q ----
#pragma unroll
    for (int i = 0; i < 4; ++i) {
        int c = t + i * 256;
        int row = c >> 2, part = c & 3;
        CP_ASYNC16(sbase + AOF_K2HI + row * 80 + part * 16,
                   g_k2hi + (size_t)b * 5120 + row * 20 + part * 4);
        CP_ASYNC16(sbase + AOF_K2LO + row * 80 + part * 16,
                   g_k2lo + (size_t)b * 5120 + row * 20 + part * 4);
        CP_ASYNC16(sbase + AOF_WO2 + row * 80 + part * 16,
                   g_wo2 + row * 20 + part * 4);
    }
    for (int c = t; c < 1056; c += 256)
        CP_ASYNC16(sbase + AOF_V2 + c * 16, g_v2 + (size_t)b * 4224 + c * 4);
    CP_COMMIT();

    {
        const float* gq = g_q + (size_t)b * 32768;
        for (int item = t; item < 2048; item += 256) {
            int kp = item >> 7, pix = item & 127;
            float f0 = gq[(2 * kp) * 1024 + pixbase + pix];
            float f1 = gq[(2 * kp + 1) * 1024 + pixbase + pix];
            uint32_t hi = f2bf2(f0, f1);
            Q2hi[pix * 20 + kp] = hi;
            Q2lo[pix * 20 + kp] = f2bf2(f0 - bf_lo(hi), f1 - bf_hi(hi));
        }
    }
    CP_WAIT0();
    __syncthreads();

    const int m0 = wid * 16;

    // Q A-fragments (reused for all kv chunks)
    uint32_t QAhi[2][4], QAlo[2][4];
#pragma unroll
    for (int ks = 0; ks < 2; ++ks) {
        const int kk = ks * 8 + tig;
        const int r0 = (m0 + g) * 20;
        const int r8 = r0 + 8 * 20;
        QAhi[ks][0] = Q2hi[r0 + kk];  QAhi[ks][1] = Q2hi[r8 + kk];
        QAhi[ks][2] = Q2hi[r0 + kk + 4]; QAhi[ks][3] = Q2hi[r8 + kk + 4];
        QAlo[ks][0] = Q2lo[r0 + kk];  QAlo[ks][1] = Q2lo[r8 + kk];
        QAlo[ks][2] = Q2lo[r0 + kk + 4]; QAlo[ks][3] = Q2lo[r8 + kk + 4];
    }

    // ---- Stages A+B fused per 64-kv chunk (warp-local, no syncs) ----
    float accB[4][4];
#pragma unroll
    for (int n2 = 0; n2 < 4; ++n2)
#pragma unroll
        for (int u = 0; u < 4; ++u) accB[n2][u] = 0.f;
    float sA = 0.f, sB = 0.f;

#pragma unroll 1
    for (int c = 0; c < 4; ++c) {
        float e[8][4];
#pragma unroll
        for (int nt = 0; nt < 8; ++nt)
#pragma unroll
            for (int u = 0; u < 4; ++u) e[nt][u] = 0.f;

#pragma unroll
        for (int ks = 0; ks < 2; ++ks) {
            const int kk = ks * 8 + tig;
#pragma unroll
            for (int nt = 0; nt < 8; ++nt) {
                const int col = (c * 64 + nt * 8 + g) * 20;
                uint32_t bh0 = K2hi[col + kk], bh1 = K2hi[col + kk + 4];
                uint32_t bl0 = K2lo[col + kk], bl1 = K2lo[col + kk + 4];
                mma16816(e[nt], QAhi[ks], bh0, bh1);
                mma16816(e[nt], QAhi[ks], bl0, bl1);
                mma16816(e[nt], QAlo[ks], bh0, bh1);
            }
        }

        // exp (no max) + pack P in registers + row sums
        uint32_t P[8][2];
#pragma unroll
        for (int nt = 0; nt < 8; ++nt) {
            float p0 = __expf(e[nt][0]);
            float p1 = __expf(e[nt][1]);
            float p2 = __expf(e[nt][2]);
            float p3 = __expf(e[nt][3]);
            sA += p0 + p1;
            sB += p2 + p3;
            P[nt][0] = f2bf2(p0, p1);
            P[nt][1] = f2bf2(p2, p3);
        }

        // B: accB += P · V over this 64-kv chunk
#pragma unroll
        for (int kt = 0; kt < 4; ++kt) {
            uint32_t a[4] = {P[2 * kt][0], P[2 * kt][1],
                             P[2 * kt + 1][0], P[2 * kt + 1][1]};
#pragma unroll
            for (int n2 = 0; n2 < 4; ++n2) {
                uint32_t b0 = V2[(n2 * 8 + g) * 132 + c * 32 + kt * 8 + tig];
                uint32_t b1 = V2[(n2 * 8 + g) * 132 + c * 32 + kt * 8 + tig + 4];
                mma16816(accB[n2], a, b0, b1);
            }
        }
    }

    // ---- normalize + pack ao into C-stage A-fragments (registers only) ----
    sA += __shfl_xor_sync(0xffffffffu, sA, 1);
    sA += __shfl_xor_sync(0xffffffffu, sA, 2);
    sB += __shfl_xor_sync(0xffffffffu, sB, 1);
    sB += __shfl_xor_sync(0xffffffffu, sB, 2);
    const float invA = 1.f / sA;
    const float invB = 1.f / sB;

    uint32_t aoHi[2][4], aoLo[2][4];
#pragma unroll
    for (int ks = 0; ks < 2; ++ks) {
        const int n2a = ks * 2, n2b = ks * 2 + 1;
        float a0 = accB[n2a][0] * invA, a1 = accB[n2a][1] * invA;
        float a2 = accB[n2a][2] * invB, a3 = accB[n2a][3] * invB;
        float a4 = accB[n2b][0] * invA, a5 = accB[n2b][1] * invA;
        float a6 = accB[n2b][2] * invB, a7 = accB[n2b][3] * invB;
        aoHi[ks][0] = f2bf2(a0, a1);
        aoHi[ks][1] = f2bf2(a2, a3);
        aoHi[ks][2] = f2bf2(a4, a5);
        aoHi[ks][3] = f2bf2(a6, a7);
        aoLo[ks][0] = f2bf2(a0 - bf_lo(aoHi[ks][0]), a1 - bf_hi(aoHi[ks][0]));
        aoLo[ks][1] = f2bf2(a2 - bf_lo(aoHi[ks][1]), a3 - bf_hi(aoHi[ks][1]));
        aoLo[ks][2] = f2bf2(a4 - bf_lo(aoHi[ks][2]), a5 - bf_hi(aoHi[ks][2]));
        aoLo[ks][3] = f2bf2(a6 - bf_lo(aoHi[ks][3]), a7 - bf_hi(aoHi[ks][3]));
    }

    // ---- Stage C: 16 px x 256 o in two halves (ao hi/lo 2-pass) ----
    const float gam = __ldg(gamma);
    const int n = b >> 6, gy = (b >> 3) & 7, gx = b & 7;
    const int pg0 = pixbase + m0 + g;
    const int i0 = pg0 >> 5, j0 = pg0 & 31;
    const size_t base0 = (size_t)n * (256 * 65536)
                       + (size_t)(gy * 32 + i0) * 256 + gx * 32 + j0;

#pragma unroll 1
    for (int hh = 0; hh < 2; ++hh) {
        float acc2[16][4];
#pragma unroll
        for (int nt = 0; nt < 16; ++nt)
#pragma unroll
            for (int u = 0; u < 4; ++u) acc2[nt][u] = 0.f;

#pragma unroll
        for (int ks = 0; ks < 2; ++ks) {
            const int kk = ks * 8 + tig;
#pragma unroll
            for (int nt = 0; nt < 16; ++nt) {
                const int col = (hh * 128 + nt * 8 + g) * 20;
                uint32_t b0 = Wo2[col + kk], b1 = Wo2[col + kk + 4];
                mma16816(acc2[nt], aoHi[ks], b0, b1);
                mma16816(acc2[nt], aoLo[ks], b0, b1);
            }
        }

#pragma unroll
        for (int nt = 0; nt < 16; ++nt) {
            const int o = hh * 128 + nt * 8 + 2 * tig;
            const float bo0 = __ldg(bo + o);
            const float bo1 = __ldg(bo + o + 1);
            const size_t a0 = base0 + (size_t)o * 65536;
            const size_t a1 = a0 + 65536;
            out[a0]     = fmaf(gam, acc2[nt][0] + bo0, x[a0]);
            out[a1]     = fmaf(gam, acc2[nt][1] + bo1, x[a1]);
            out[a0 + 8] = fmaf(gam, acc2[nt][2] + bo0, x[a0 + 8]);
            out[a1 + 8] = fmaf(gam, acc2[nt][3] + bo1, x[a1 + 8]);
        }
    }
}

// ---------------------------------------------------------------------------
extern "C" void kernel_launch(void* const* d_in, const int* in_sizes, int n_in,
                              void* d_out, int out_size)
{
    const float* x  = (const float*)d_in[0];
    const float* Wq = (const float*)d_in[1];
    const float* bq = (const float*)d_in[2];
    const float* Wk = (const float*)d_in[3];
    const float* bk = (const float*)d_in[4];
    const float* Wv = (const float*)d_in[5];
    const float* bv = (const float*)d_in[6];
    const float* Wo = (const float*)d_in[7];
    const float* bo = (const float*)d_in[8];
    const float* gamma = (const float*)d_in[9];
    float* out = (float*)d_out;

    cudaFuncSetAttribute(qkv_mma_kernel, cudaFuncAttributeMaxDynamicSharedMemorySize, QKV_SMEM);
    cudaFuncSetAttribute(pool_pack_kernel, cudaFuncAttributeMaxDynamicSharedMemorySize, POOL_SMEM);
    cudaFuncSetAttribute(attn_mma_kernel, cudaFuncAttributeMaxDynamicSharedMemorySize, ATTN_SMEM);

    qkv_mma_kernel<<<2048, 512, QKV_SMEM>>>(x, Wq, bq, Wk, bk, Wv, bv);
    pool_pack_kernel<<<513, 256, POOL_SMEM>>>(Wo);
    attn_mma_kernel<<<4096, 256, ATTN_SMEM>>>(bo, gamma, x, out);
}

// round 17
// speedup vs baseline: 1.5632x; 1.0725x over previous
#include <cuda_runtime.h>
#include <cuda_bf16.h>
#include <math.h>
#include <cstdint>

// Problem constants
#define NB 8
#define CIN 256
#define HW 65536
#define NCH 512
#define CQK 32
#define NQ 1024
#define NKV 256

// Scratch (device globals; no allocation allowed)
__device__ float g_q [(size_t)NCH * CQK * NQ];       // [b][ch][pix] fp32
__device__ float g_kf[(size_t)NCH * CQK * NQ];       // [b][ch][pix] fp32 (pre-pool)
__device__ float g_vf[(size_t)NCH * CQK * NQ];       // [b][ch][pix] fp32 (pre-pool)
__device__ uint32_t g_k2hi[(size_t)NCH * NKV * 20];  // [b][kv][20] bf16-pair hi
__device__ uint32_t g_k2lo[(size_t)NCH * NKV * 20];  // [b][kv][20] bf16-pair lo
__device__ uint32_t g_v2  [(size_t)NCH * 32 * 132];  // [b][ch][132] bf16 kv-pairs
__device__ uint32_t g_wo2 [256 * 20];                // [o][20] bf16 ch-pairs

// ===========================================================================
// helpers
// ===========================================================================
__device__ __forceinline__ uint32_t s2u32(const void* p) {
    uint32_t a;
    asm("{ .reg .u64 t; cvta.to.shared.u64 t, %1; cvt.u32.u64 %0, t; }" : "=r"(a) : "l"(p));
    return a;
}
__device__ __forceinline__ uint32_t f2bf2(float lo, float hi) {
    uint32_t r;
    asm("cvt.rn.bf16x2.f32 %0, %1, %2;" : "=r"(r) : "f"(hi), "f"(lo));
    return r;
}
__device__ __forceinline__ float bf_lo(uint32_t h) { return __uint_as_float(h << 16); }
__device__ __forceinline__ float bf_hi(uint32_t h) { return __uint_as_float(h & 0xffff0000u); }

__device__ __forceinline__ void mma16816(float* c, const uint32_t* a, uint32_t b0, uint32_t b1) {
    asm volatile(
        "mma.sync.aligned.m16n8k16.row.col.f32.bf16.bf16.f32 "
        "{%0,%1,%2,%3}, {%4,%5,%6,%7}, {%8,%9}, {%0,%1,%2,%3};"
        : "+f"(c[0]), "+f"(c[1]), "+f"(c[2]), "+f"(c[3])
        : "r"(a[0]), "r"(a[1]), "r"(a[2]), "r"(a[3]), "r"(b0), "r"(b1));
}

#define CP_ASYNC16(dst, src) \
    asm volatile("cp.async.ca.shared.global [%0], [%1], 16;" :: "r"(dst), "l"(src) : "memory")
#define CP_COMMIT() asm volatile("cp.async.commit_group;" ::: "memory")
#define CP_WAIT0()  asm volatile("cp.async.wait_group 0;" ::: "memory")

// ===========================================================================
// Kernel 1: q/k/v projection via mma.sync bf16 hi/lo 3-pass.
// 512 threads = 16 warps: warpM(2, 48 rows) x warpN(8, 32 px). K=256.
// Inner loop restructured: convert all B-frags, then 3 passes of 12
// independent MMAs (RAW distance 12 instead of 1).
// ===========================================================================
#define OFF_W2HI  0
#define OFF_W2LO  50688
#define OFF_BIAS  101376
#define OFF_XS    101760
#define XS_FLOATS 8576
#define QKV_SMEM  170368

__global__ __launch_bounds__(512, 1)
void qkv_mma_kernel(const float* __restrict__ x,
                    const float* __restrict__ Wq, const float* __restrict__ bq,
                    const float* __restrict__ Wk, const float* __restrict__ bk,
                    const float* __restrict__ Wv, const float* __restrict__ bv)
{
    extern __shared__ __align__(16) char smem[];
    const uint32_t sbase = s2u32(smem);
    uint32_t* W2hi = (uint32_t*)(smem + OFF_W2HI);
    uint32_t* W2lo = (uint32_t*)(smem + OFF_W2LO);
    float*    bias = (float*)(smem + OFF_BIAS);
    float*    xsm  = (float*)(smem + OFF_XS);

    const int t = threadIdx.x;
    const int wid = t >> 5, lane = t & 31;
    const int g = lane >> 2, tig = lane & 3;
    const int warpM = wid >> 3, warpN = wid & 7;
    const int m0 = warpM * 48;
    const int n0w = warpN * 32;

    const int bid = blockIdx.x;
    const int h = bid & 255;
    const int n = bid >> 8;

    const float* xrow = x + (size_t)n * (256 * 65536) + (size_t)h * 256;

    {
        const uint32_t dstb = sbase + OFF_XS;
#pragma unroll
        for (int i = 0; i < 4; ++i) {
            int item = t + i * 512;
            int ch = item >> 6, p4 = item & 63;
            CP_ASYNC16(dstb + (uint32_t)(ch * 268 + p4 * 4) * 4,
                       xrow + (size_t)ch * 65536 + p4 * 4);
        }
        CP_COMMIT();
    }

    for (int item = t; item < 96 * 128; item += 512) {
        int m = item >> 7, kk = item & 127;
        const float* wrow = (m < 32) ? (Wq + m * 256)
                          : (m < 64) ? (Wk + (m - 32) * 256)
                                     : (Wv + (m - 64) * 256);
        float f0 = wrow[2 * kk], f1 = wrow[2 * kk + 1];
        uint32_t hi = f2bf2(f0, f1);
        uint32_t lo = f2bf2(f0 - bf_lo(hi), f1 - bf_hi(hi));
        W2hi[m * 132 + kk] = hi;
        W2lo[m * 132 + kk] = lo;
    }
    if (t < 96) bias[t] = (t < 32) ? bq[t] : (t < 64 ? bk[t - 32] : bv[t - 64]);

    float acc[3][4][4];
#pragma unroll
    for (int mt = 0; mt < 3; ++mt)
#pragma unroll
        for (int nt = 0; nt < 4; ++nt)
#pragma unroll
            for (int u = 0; u < 4; ++u) acc[mt][nt][u] = 0.f;

    CP_WAIT0();
    __syncthreads();

#pragma unroll 1
    for (int cc = 0; cc < 8; ++cc) {
        if (cc < 7) {
            const uint32_t dstb = sbase + OFF_XS + (uint32_t)(((cc + 1) & 1) * XS_FLOATS * 4);
            const float* srcb = xrow + (size_t)(cc + 1) * 32 * 65536;
#pragma unroll
            for (int i = 0; i < 4; ++i) {
                int item = t + i * 512;
                int ch = item >> 6, p4 = item & 63;
                CP_ASYNC16(dstb + (uint32_t)(ch * 268 + p4 * 4) * 4,
                           srcb + (size_t)ch * 65536 + p4 * 4);
            }
            CP_COMMIT();
        }

        const float* xsf = xsm + (cc & 1) * XS_FLOATS;
        const int kkc = cc * 16;

#pragma unroll
        for (int s = 0; s < 2; ++s) {
            const int ks = s * 16;
            const int kk0 = kkc + s * 8 + tig;

            // ---- convert all 4 B-fragments first ----
            uint32_t bhi[4][2], blo[4][2];
#pragma unroll
            for (int nt = 0; nt < 4; ++nt) {
                const int base = (ks + 2 * tig) * 268 + n0w + nt * 8 + g;
                float x0 = xsf[base];
                float x1 = xsf[base + 268];
                float x2 = xsf[base + 8 * 268];
                float x3 = xsf[base + 9 * 268];
                bhi[nt][0] = f2bf2(x0, x1);
                bhi[nt][1] = f2bf2(x2, x3);
                blo[nt][0] = f2bf2(x0 - bf_lo(bhi[nt][0]), x1 - bf_hi(bhi[nt][0]));
                blo[nt][1] = f2bf2(x2 - bf_lo(bhi[nt][1]), x3 - bf_hi(bhi[nt][1]));
            }

            // ---- A fragments ----
            uint32_t Ahi[3][4], Alo[3][4];
#pragma unroll
            for (int mt = 0; mt < 3; ++mt) {
                const int r0 = (m0 + mt * 16 + g) * 132;
                const int r8 = r0 + 8 * 132;
                Ahi[mt][0] = W2hi[r0 + kk0];
                Ahi[mt][1] = W2hi[r8 + kk0];
                Ahi[mt][2] = W2hi[r0 + kk0 + 4];
                Ahi[mt][3] = W2hi[r8 + kk0 + 4];
                Alo[mt][0] = W2lo[r0 + kk0];
                Alo[mt][1] = W2lo[r8 + kk0];
                Alo[mt][2] = W2lo[r0 + kk0 + 4];
                Alo[mt][3] = W2lo[r8 + kk0 + 4];
            }

            // ---- 3 passes of 12 independent MMAs ----
#pragma unroll
            for (int mt = 0; mt < 3; ++mt)
#pragma unroll
                for (int nt = 0; nt < 4; ++nt)
                    mma16816(acc[mt][nt], Ahi[mt], bhi[nt][0], bhi[nt][1]);
#pragma unroll
            for (int mt = 0; mt < 3; ++mt)
#pragma unroll
                for (int nt = 0; nt < 4; ++nt)
                    mma16816(acc[mt][nt], Ahi[mt], blo[nt][0], blo[nt][1]);
#pragma unroll
            for (int mt = 0; mt < 3; ++mt)
#pragma unroll
                for (int nt = 0; nt < 4; ++nt)
                    mma16816(acc[mt][nt], Alo[mt], bhi[nt][0], bhi[nt][1]);
        }

        if (cc < 7) CP_WAIT0();
        __syncthreads();
    }

    {
        const int gy = h >> 5, ii = h & 31;
#pragma unroll
        for (int mt = 0; mt < 3; ++mt) {
            const int mbase = m0 + mt * 16;
            const int aidx = mbase >> 5;
            float* arr = (aidx == 0) ? g_q : (aidx == 1) ? g_kf : g_vf;
            const int ch = (mbase & 31) + g;
            const float b1 = bias[mbase + g];
            const float b2 = bias[mbase + 8 + g];
#pragma unroll
            for (int nt = 0; nt < 4; ++nt) {
                const int w = n0w + nt * 8 + tig * 2;
                const int gx = w >> 5;
                const int b = n * 64 + gy * 8 + gx;
                const int pix = ii * 32 + (w & 31);
                float2* d0 = (float2*)(arr + ((size_t)(b * 32 + ch)) * 1024 + pix);
                float2* d1 = (float2*)(arr + ((size_t)(b * 32 + ch + 8)) * 1024 + pix);
                *d0 = make_float2(acc[mt][nt][0] + b1, acc[mt][nt][1] + b1);
                *d1 = make_float2(acc[mt][nt][2] + b2, acc[mt][nt][3] + b2);
            }
        }
    }
}

// ===========================================================================
// Kernel 2: pool + pack, 4 CTAs per chunk (8-channel slices) for occupancy.
// Grid 2049: bid<2048 -> chunk b = bid>>2, slice s = bid&3. bid 2048 -> Wo.
// ===========================================================================
#define POOL_STRIDE 1028
#define POOL_SMEM  (8 * POOL_STRIDE * 4)

__global__ __launch_bounds__(256)
void pool_pack_kernel(const float* __restrict__ Wo)
{
    extern __shared__ float ps[];
    const int t = threadIdx.x;
    const int bid = blockIdx.x;

    if (bid < 2048) {
        const int b = bid >> 2, s = bid & 3;
        const int ch0 = s * 8;

        // ---- K slice: stage 8 channels ----
        const float4* src = (const float4*)(g_kf + (size_t)b * 32768 + (size_t)ch0 * 1024);
        for (int i = t; i < 2048; i += 256) {
            int ch = i >> 8, p4 = i & 255;
            ((float4*)ps)[ch * 257 + p4] = src[ch * 256 + p4];
        }
        __syncthreads();
        for (int i = t; i < 1024; i += 256) {
            int kp_l = i & 3, kv = i >> 2;
            int pi = kv >> 4, pj = kv & 15;
            const float* r0 = ps + (2 * kp_l) * POOL_STRIDE + pi * 64 + 2 * pj;
            const float* r1 = r0 + POOL_STRIDE;
            float m0 = fmaxf(fmaxf(r0[0], r0[1]), fmaxf(r0[32], r0[33]));
            float m1 = fmaxf(fmaxf(r1[0], r1[1]), fmaxf(r1[32], r1[33]));
            uint32_t hi = f2bf2(m0, m1);
            uint32_t lo = f2bf2(m0 - bf_lo(hi), m1 - bf_hi(hi));
            const int kp = s * 4 + kp_l;
            g_k2hi[(size_t)b * 5120 + kv * 20 + kp] = hi;
            g_k2lo[(size_t)b * 5120 + kv * 20 + kp] = lo;
        }
        __syncthreads();

        // ---- V slice ----
        const float4* srcv = (const float4*)(g_vf + (size_t)b * 32768 + (size_t)ch0 * 1024);
        for (int i = t; i < 2048; i += 256) {
            int ch = i >> 8, p4 = i & 255;
            ((float4*)ps)[ch * 257 + p4] = srcv[ch * 256 + p4];
        }
        __syncthreads();
        for (int i = t; i < 1024; i += 256) {
            int ch_l = i >> 7, kvp = i & 127;
            const float* rr = ps + ch_l * POOL_STRIDE;
            int kv0 = 2 * kvp, kv1 = kv0 + 1;
            int b0 = (kv0 >> 4) * 64 + 2 * (kv0 & 15);
            int b1i = (kv1 >> 4) * 64 + 2 * (kv1 & 15);
            float v0 = fmaxf(fmaxf(rr[b0], rr[b0 + 1]), fmaxf(rr[b0 + 32], rr[b0 + 33]));
            float v1 = fmaxf(fmaxf(rr[b1i], rr[b1i + 1]), fmaxf(rr[b1i + 32], rr[b1i + 33]));
            g_v2[(size_t)b * 4224 + (ch0 + ch_l) * 132 + kvp] = f2bf2(v0, v1);
        }
    } else {
        for (int i = t; i < 4096; i += 256) {
            int kp = i & 15, o = i >> 4;
            g_wo2[o * 20 + kp] = f2bf2(Wo[o * 32 + 2 * kp], Wo[o * 32 + 2 * kp + 1]);
        }
    }
}

// ===========================================================================
// Kernel 3: attention, flash-style, 256 threads = 8 warps, 2 CTAs/SM.
// (round-16, passing)
// ===========================================================================
#define AOF_Q2HI 0          // [128][20] u32
#define AOF_Q2LO 10240
#define AOF_K2HI 20480      // [256][20] u32
#define AOF_K2LO 40960
#define AOF_V2   61440      // [32][132] u32
#define AOF_WO2  78336      // [256][20] u32
#define ATTN_SMEM 98816

__global__ __launch_bounds__(256, 2)
void attn_mma_kernel(const float* __restrict__ bo,
                     const float* __restrict__ gamma,
                     const float* __restrict__ x, float* __restrict__ out)
{
    extern __shared__ __align__(16) char smem[];
    const uint32_t sbase = s2u32(smem);
    uint32_t* Q2hi = (uint32_t*)(smem + AOF_Q2HI);
    uint32_t* Q2lo = (uint32_t*)(smem + AOF_Q2LO);
    uint32_t* K2hi = (uint32_t*)(smem + AOF_K2HI);
    uint32_t* K2lo = (uint32_t*)(smem + AOF_K2LO);
    uint32_t* V2   = (uint32_t*)(smem + AOF_V2);
    uint32_t* Wo2  = (uint32_t*)(smem + AOF_WO2);

    const int t = threadIdx.x;
    const int wid = t >> 5, lane = t & 31;
    const int g = lane >> 2, tig = lane & 3;

    const int bid = blockIdx.x;
    const int b = bid >> 3;
    const int pixbase = (bid & 7) << 7;

    // ---- Phase 0: cp.async K2/V2/Wo2, convert Q ----
#pragma unroll
    for (int i = 0; i < 4; ++i) {
        int c = t + i * 256;
        int row = c >> 2, part = c & 3;
        CP_ASYNC16(sbase + AOF_K2HI + row * 80 + part * 16,
                   g_k2hi + (size_t)b * 5120 + row * 20 + part * 4);
        CP_ASYNC16(sbase + AOF_K2LO + row * 80 + part * 16,
                   g_k2lo + (size_t)b * 5120 + row * 20 + part * 4);
        CP_ASYNC16(sbase + AOF_WO2 + row * 80 + part * 16,
                   g_wo2 + row * 20 + part * 4);
    }
    for (int c = t; c < 1056; c += 256)
        CP_ASYNC16(sbase + AOF_V2 + c * 16, g_v2 + (size_t)b * 4224 + c * 4);
    CP_COMMIT();

    {
        const float* gq = g_q + (size_t)b * 32768;
        for (int item = t; item < 2048; item += 256) {
            int kp = item >> 7, pix = item & 127;
            float f0 = gq[(2 * kp) * 1024 + pixbase + pix];
            float f1 = gq[(2 * kp + 1) * 1024 + pixbase + pix];
            uint32_t hi = f2bf2(f0, f1);
            Q2hi[pix * 20 + kp] = hi;
            Q2lo[pix * 20 + kp] = f2bf2(f0 - bf_lo(hi), f1 - bf_hi(hi));
        }
    }
    CP_WAIT0();
    __syncthreads();

    const int m0 = wid * 16;

    uint32_t QAhi[2][4], QAlo[2][4];
#pragma unroll
    for (int ks = 0; ks < 2; ++ks) {
        const int kk = ks * 8 + tig;
        const int r0 = (m0 + g) * 20;
        const int r8 = r0 + 8 * 20;
        QAhi[ks][0] = Q2hi[r0 + kk];  QAhi[ks][1] = Q2hi[r8 + kk];
        QAhi[ks][2] = Q2hi[r0 + kk + 4]; QAhi[ks][3] = Q2hi[r8 + kk + 4];
        QAlo[ks][0] = Q2lo[r0 + kk];  QAlo[ks][1] = Q2lo[r8 + kk];
        QAlo[ks][2] = Q2lo[r0 + kk + 4]; QAlo[ks][3] = Q2lo[r8 + kk + 4];
    }

    float accB[4][4];
#pragma unroll
    for (int n2 = 0; n2 < 4; ++n2)
#pragma unroll
        for (int u = 0; u < 4; ++u) accB[n2][u] = 0.f;
    float sA = 0.f, sB = 0.f;

#pragma unroll 1
    for (int c = 0; c < 4; ++c) {
        float e[8][4];
#pragma unroll
        for (int nt = 0; nt < 8; ++nt)
#pragma unroll
            for (int u = 0; u < 4; ++u) e[nt][u] = 0.f;

#pragma unroll
        for (int ks = 0; ks < 2; ++ks) {
            const int kk = ks * 8 + tig;
#pragma unroll
            for (int nt = 0; nt < 8; ++nt) {
                const int col = (c * 64 + nt * 8 + g) * 20;
                uint32_t bh0 = K2hi[col + kk], bh1 = K2hi[col + kk + 4];
                uint32_t bl0 = K2lo[col + kk], bl1 = K2lo[col + kk + 4];
                mma16816(e[nt], QAhi[ks], bh0, bh1);
                mma16816(e[nt], QAhi[ks], bl0, bl1);
                mma16816(e[nt], QAlo[ks], bh0, bh1);
            }
        }

        uint32_t P[8][2];
#pragma unroll
        for (int nt = 0; nt < 8; ++nt) {
            float p0 = __expf(e[nt][0]);
            float p1 = __expf(e[nt][1]);
            float p2 = __expf(e[nt][2]);
            float p3 = __expf(e[nt][3]);
            sA += p0 + p1;
            sB += p2 + p3;
            P[nt][0] = f2bf2(p0, p1);
            P[nt][1] = f2bf2(p2, p3);
        }

#pragma unroll
        for (int kt = 0; kt < 4; ++kt) {
            uint32_t a[4] = {P[2 * kt][0], P[2 * kt][1],
                             P[2 * kt + 1][0], P[2 * kt + 1][1]};
#pragma unroll
            for (int n2 = 0; n2 < 4; ++n2) {
                uint32_t b0 = V2[(n2 * 8 + g) * 132 + c * 32 + kt * 8 + tig];
                uint32_t b1 = V2[(n2 * 8 + g) * 132 + c * 32 + kt * 8 + tig + 4];
                mma16816(accB[n2], a, b0, b1);
            }
        }
    }

    sA += __shfl_xor_sync(0xffffffffu, sA, 1);
    sA += __shfl_xor_sync(0xffffffffu, sA, 2);
    sB += __shfl_xor_sync(0xffffffffu, sB, 1);
    sB += __shfl_xor_sync(0xffffffffu, sB, 2);
    const float invA = 1.f / sA;
    const float invB = 1.f / sB;

    uint32_t aoHi[2][4], aoLo[2][4];
#pragma unroll
    for (int ks = 0; ks < 2; ++ks) {
        const int n2a = ks * 2, n2b = ks * 2 + 1;
        float a0 = accB[n2a][0] * invA, a1 = accB[n2a][1] * invA;
        float a2 = accB[n2a][2] * invB, a3 = accB[n2a][3] * invB;
        float a4 = accB[n2b][0] * invA, a5 = accB[n2b][1] * invA;
        float a6 = accB[n2b][2] * invB, a7 = accB[n2b][3] * invB;
        aoHi[ks][0] = f2bf2(a0, a1);
        aoHi[ks][1] = f2bf2(a2, a3);
        aoHi[ks][2] = f2bf2(a4, a5);
        aoHi[ks][3] = f2bf2(a6, a7);
        aoLo[ks][0] = f2bf2(a0 - bf_lo(aoHi[ks][0]), a1 - bf_hi(aoHi[ks][0]));
        aoLo[ks][1] = f2bf2(a2 - bf_lo(aoHi[ks][1]), a3 - bf_hi(aoHi[ks][1]));
        aoLo[ks][2] = f2bf2(a4 - bf_lo(aoHi[ks][2]), a5 - bf_hi(aoHi[ks][2]));
        aoLo[ks][3] = f2bf2(a6 - bf_lo(aoHi[ks][3]), a7 - bf_hi(aoHi[ks][3]));
    }

    const float gam = __ldg(gamma);
    const int n = b >> 6, gy = (b >> 3) & 7, gx = b & 7;
    const int pg0 = pixbase + m0 + g;
    const int i0 = pg0 >> 5, j0 = pg0 & 31;
    const size_t base0 = (size_t)n * (256 * 65536)
                       + (size_t)(gy * 32 + i0) * 256 + gx * 32 + j0;

#pragma unroll 1
    for (int hh = 0; hh < 2; ++hh) {
        float acc2[16][4];
#pragma unroll
        for (int nt = 0; nt < 16; ++nt)
#pragma unroll
            for (int u = 0; u < 4; ++u) acc2[nt][u] = 0.f;

#pragma unroll
        for (int ks = 0; ks < 2; ++ks) {
            const int kk = ks * 8 + tig;
#pragma unroll
            for (int nt = 0; nt < 16; ++nt) {
                const int col = (hh * 128 + nt * 8 + g) * 20;
                uint32_t b0 = Wo2[col + kk], b1 = Wo2[col + kk + 4];
                mma16816(acc2[nt], aoHi[ks], b0, b1);
                mma16816(acc2[nt], aoLo[ks], b0, b1);
            }
        }

#pragma unroll
        for (int nt = 0; nt < 16; ++nt) {
            const int o = hh * 128 + nt * 8 + 2 * tig;
            const float bo0 = __ldg(bo + o);
            const float bo1 = __ldg(bo + o + 1);
            const size_t a0 = base0 + (size_t)o * 65536;
            const size_t a1 = a0 + 65536;
            out[a0]     = fmaf(gam, acc2[nt][0] + bo0, x[a0]);
            out[a1]     = fmaf(gam, acc2[nt][1] + bo1, x[a1]);
            out[a0 + 8] = fmaf(gam, acc2[nt][2] + bo0, x[a0 + 8]);
            out[a1 + 8] = fmaf(gam, acc2[nt][3] + bo1, x[a1 + 8]);
        }
    }
}

// ---------------------------------------------------------------------------
extern "C" void kernel_launch(void* const* d_in, const int* in_sizes, int n_in,
                              void* d_out, int out_size)
{
    const float* x  = (const float*)d_in[0];
    const float* Wq = (const float*)d_in[1];
    const float* bq = (const float*)d_in[2];
    const float* Wk = (const float*)d_in[3];
    const float* bk = (const float*)d_in[4];
    const float* Wv = (const float*)d_in[5];
    const float* bv = (const float*)d_in[6];
    const float* Wo = (const float*)d_in[7];
    const float* bo = (const float*)d_in[8];
    const float* gamma = (const float*)d_in[9];
    float* out = (float*)d_out;

    cudaFuncSetAttribute(qkv_mma_kernel, cudaFuncAttributeMaxDynamicSharedMemorySize, QKV_SMEM);
    cudaFuncSetAttribute(pool_pack_kernel, cudaFuncAttributeMaxDynamicSharedMemorySize, POOL_SMEM);
    cudaFuncSetAttribute(attn_mma_kernel, cudaFuncAttributeMaxDynamicSharedMemorySize, ATTN_SMEM);

    qkv_mma_kernel<<<2048, 512, QKV_SMEM>>>(x, Wq, bq, Wk, bk, Wv, bv);
    pool_pack_kernel<<<2049, 256, POOL_SMEM>>>(Wo);
    attn_mma_kernel<<<4096, 256, ATTN_SMEM>>>(bo, gamma, x, out);
}